// round 11
// baseline (speedup 1.0000x reference)
#include <cuda_runtime.h>
#include <cstdint>

// ---------------------------------------------------------------------------
// SimpleESN: h_t = (1-a) h_{t-1} + a * tanh(W_in x_t + W h_{t-1})
//
// R11 = R10 + column indices ALSO hoisted to registers (they are loop-
// invariant, same as the values). The 2048-step gather loop now performs
// ZERO global loads beyond the 16KB h-stage and one x float4:
//   per iter: unpack cc (ALU), 2x LDS (conflict-free), 2x FFMA.
//  - ROW_CAP fixed 512 -> uniform 8 iters/warp (no length stragglers)
//  - V[8] float2 value regs + C[8] packed u32 col regs (~64 regs total,
//    the exact ceiling for a 1024-thread block)
//  - sync: R5/R10 proven scheme (single counter, one spinner, bulk stage)
// ---------------------------------------------------------------------------

#define T_STEPS 2048
#define N_RES   4096
#define N_IN    128
#define LEAK    0.3f

#define BLOCKS  128
#define THREADS 1024
#define WARPS   (THREADS / 32)                 // 32
#define ROWS_PER_BLOCK (N_RES / BLOCKS)        // 32 -> 1 row per warp
#define ROW_CAP 512                            // FIXED: 8 iters for all rows

__device__ uint2          g_tmp[(size_t)N_RES * ROW_CAP];   // build scratch
__device__ float          g_val[(size_t)N_RES * ROW_CAP];
__device__ unsigned short g_col[(size_t)N_RES * ROW_CAP];
__device__ unsigned int   g_barrier;

__global__ void esn_reset_kernel() { g_barrier = 0u; }

__device__ __forceinline__ unsigned int ld_relaxed_gpu(const unsigned int* p) {
    unsigned int v;
    asm volatile("ld.relaxed.gpu.global.u32 %0, [%1];" : "=r"(v) : "l"(p) : "memory");
    return v;
}
__device__ __forceinline__ void red_release_gpu_add(unsigned int* p, unsigned int v) {
    asm volatile("red.release.gpu.global.add.u32 [%0], %1;" :: "l"(p), "r"(v) : "memory");
}

__global__ void __launch_bounds__(THREADS, 1)
esn_kernel(const float* __restrict__ x,
           const float* __restrict__ W_in,
           const float* __restrict__ W,
           float* __restrict__ out)
{
    __shared__ float h_sm[N_RES];                      // 16 KB
    __shared__ int   cnt_sm[WARPS * 32];               // 4 KB: build-phase bins

    const int tid  = threadIdx.x;
    const int wid  = tid >> 5;
    const int lane = tid & 31;
    const int row0 = blockIdx.x * ROWS_PER_BLOCK;
    const int row  = row0 + wid;
    const size_t rowbase = (size_t)row * ROW_CAP;

    // ------------------------------------------------------------------
    // Phase 1: compact row -> g_tmp (ascending cols), count nnz
    // ------------------------------------------------------------------
    int len = 0;
    {
        const float* wrow = W + (size_t)row * N_RES;
        uint2* tmp = g_tmp + rowbase;
        int cnt = 0;
        #pragma unroll 4
        for (int c0 = 0; c0 < N_RES; c0 += 32) {
            float v = wrow[c0 + lane];
            unsigned m = __ballot_sync(0xffffffffu, v != 0.0f);
            if (v != 0.0f) {
                int pos = cnt + __popc(m & ((1u << lane) - 1u));
                if (pos < ROW_CAP)
                    tmp[pos] = make_uint2(__float_as_uint(v), (unsigned)(c0 + lane));
            }
            cnt += __popc(m);
        }
        len = (cnt < ROW_CAP) ? cnt : ROW_CAP;
    }

    // ------------------------------------------------------------------
    // Phase 1.5: bank round-robin reorder, SoA scatter, fixed 512 pad
    //   pos sorted by (m, bank); sigma: pos = 64k + 32c + l -> s = 64k + 2l + c
    //   pad entries: val=0, col=0 (smem broadcast, conflict-free)
    // ------------------------------------------------------------------
    {
        int* cnt = cnt_sm + wid * 32;
        cnt[lane] = 0;
        __syncwarp();

        uint2* tmp = g_tmp + rowbase;
        for (int j = lane; j < len; j += 32) {          // pass A: within-bank idx
            uint2 e = tmp[j];
            int b = (int)(e.y & 31u);
            int m = atomicAdd(&cnt[b], 1);
            tmp[j].y = e.y | ((unsigned)m << 16);
        }
        __syncwarp();

        for (int j = lane; j < ROW_CAP; j += 32) {      // zero-fill all 512
            g_val[rowbase + j] = 0.0f;
            g_col[rowbase + j] = 0;
        }
        __syncwarp();

        for (int j = lane; j < len; j += 32) {          // pass B: rank+sigma+scatter
            uint2 e = tmp[j];
            int col = (int)(e.y & 0xFFFu);
            int m   = (int)(e.y >> 16);
            int b   = col & 31;
            int pos = 0;
            #pragma unroll
            for (int b2 = 0; b2 < 32; ++b2) {
                int c = cnt[b2];
                pos += (c < m ? c : m) + (int)((b2 < b) && (c > m));
            }
            int s = (pos & ~63) | ((pos & 31) << 1) | ((pos >> 5) & 1);
            g_val[rowbase + s] = __uint_as_float(e.x);
            g_col[rowbase + s] = (unsigned short)col;
        }
    }
    __syncthreads();

    // ------------------------------------------------------------------
    // Hoist ALL loop-invariant data into registers: W_in row, values, cols
    // ------------------------------------------------------------------
    const float a  = LEAK;
    const float ia = 1.0f - LEAK;
    const float4 w4 = __ldg((const float4*)(W_in + (size_t)row * N_IN) + lane);

    float2       V[8];                                 // 16 value regs
    unsigned int C[8];                                 // 16 cols in 8 packed regs
    {
        const float2*       vp = (const float2*)(g_val + rowbase);
        const unsigned int* cp = (const unsigned int*)(g_col + rowbase);
        #pragma unroll
        for (int k = 0; k < 8; ++k) {
            V[k] = vp[(k << 5) + lane];
            C[k] = cp[(k << 5) + lane];
        }
    }

    // ------------------------------------------------------------------
    // Phase 2: time recurrence (sync scheme identical to R5/R10)
    // ------------------------------------------------------------------
    for (int t = 0; t < T_STEPS; ++t) {
        // h-independent dense part (overlaps the wait below)
        float4 x4 = __ldg((const float4*)(x + (size_t)t * N_IN) + lane);
        float sum0 = w4.x * x4.x + w4.y * x4.y;
        float sum1 = w4.z * x4.z + w4.w * x4.w;

        // global gate: single spinner on the single counter
        if (t > 0) {
            if (tid == 0) {
                const unsigned int want = (unsigned int)t * BLOCKS;
                while (ld_relaxed_gpu(&g_barrier) < want) { }
            }
            __syncthreads();   // S1
        }

        // bulk stage h_{t-1} into smem (L2-direct, always coherent)
        if (t == 0) {
            for (int i = tid; i < N_RES; i += THREADS) h_sm[i] = 0.0f;
        } else {
            const float4* hprev = (const float4*)(out + (size_t)(t - 1) * N_RES);
            float4 v = __ldcg(hprev + tid);
            *(float4*)(h_sm + tid * 4) = v;
        }
        __syncthreads();       // S2

        // pure-register gather: unpack, 2x conflict-free LDS, 2x FFMA per iter
        #pragma unroll
        for (int k = 0; k < 8; ++k) {
            sum0 = fmaf(V[k].x, h_sm[C[k] & 0xFFFFu], sum0);
            sum1 = fmaf(V[k].y, h_sm[C[k] >> 16],     sum1);
        }

        // butterfly warp reduce
        float sum = sum0 + sum1;
        #pragma unroll
        for (int o = 16; o > 0; o >>= 1)
            sum += __shfl_xor_sync(0xffffffffu, sum, o);

        if (lane == 0) {
            float hn = ia * h_sm[row] + a * tanhf(sum);
            __stcg(out + (size_t)t * N_RES + row, hn);
        }

        if (t < T_STEPS - 1) {
            __syncthreads();                 // S3: all rows of this block in L2
            if (tid == 0) red_release_gpu_add(&g_barrier, 1u);
        }
    }
}

extern "C" void kernel_launch(void* const* d_in, const int* in_sizes, int n_in,
                              void* d_out, int out_size)
{
    const float* x    = (const float*)d_in[0];   // [2048, 128]
    const float* W_in = (const float*)d_in[1];   // [4096, 128]
    const float* W    = (const float*)d_in[2];   // [4096, 4096]
    float* out        = (float*)d_out;           // [2048, 4096]

    esn_reset_kernel<<<1, 1>>>();
    esn_kernel<<<BLOCKS, THREADS>>>(x, W_in, W, out);
}

// round 12
// speedup vs baseline: 1.1414x; 1.1414x over previous
#include <cuda_runtime.h>
#include <cstdint>

// ---------------------------------------------------------------------------
// SimpleESN: h_t = (1-a) h_{t-1} + a * tanh(W_in x_t + W h_{t-1})
//
// R12 = R10 (best: V-hoisted, cols LDG'd per step, uniform 8 iters,
// single-counter relay) + two serial-path fixes:
//  - x_t prefetched one step ahead -> the spinner's poll is never delayed
//    by an x L2/DRAM miss (previously up to ~577 cyc on the gate, every step)
//  - 2-deep staggered poll: two relaxed loads in flight, check the older
//    while the newer flies -> detection quantization ~130 cyc instead of ~262
// ---------------------------------------------------------------------------

#define T_STEPS 2048
#define N_RES   4096
#define N_IN    128
#define LEAK    0.3f

#define BLOCKS  128
#define THREADS 1024
#define WARPS   (THREADS / 32)                 // 32
#define ROWS_PER_BLOCK (N_RES / BLOCKS)        // 32 -> 1 row per warp
#define ROW_CAP 512                            // FIXED: 8 iters for all rows

__device__ uint2          g_tmp[(size_t)N_RES * ROW_CAP];   // build scratch
__device__ float          g_val[(size_t)N_RES * ROW_CAP];
__device__ unsigned short g_col[(size_t)N_RES * ROW_CAP];
__device__ unsigned int   g_barrier;

__global__ void esn_reset_kernel() { g_barrier = 0u; }

__device__ __forceinline__ unsigned int ld_relaxed_gpu(const unsigned int* p) {
    unsigned int v;
    asm volatile("ld.relaxed.gpu.global.u32 %0, [%1];" : "=r"(v) : "l"(p) : "memory");
    return v;
}
__device__ __forceinline__ void red_release_gpu_add(unsigned int* p, unsigned int v) {
    asm volatile("red.release.gpu.global.add.u32 [%0], %1;" :: "l"(p), "r"(v) : "memory");
}

__global__ void __launch_bounds__(THREADS, 1)
esn_kernel(const float* __restrict__ x,
           const float* __restrict__ W_in,
           const float* __restrict__ W,
           float* __restrict__ out)
{
    __shared__ float h_sm[N_RES];                      // 16 KB
    __shared__ int   cnt_sm[WARPS * 32];               // 4 KB: build-phase bins

    const int tid  = threadIdx.x;
    const int wid  = tid >> 5;
    const int lane = tid & 31;
    const int row0 = blockIdx.x * ROWS_PER_BLOCK;
    const int row  = row0 + wid;
    const size_t rowbase = (size_t)row * ROW_CAP;

    // ------------------------------------------------------------------
    // Phase 1: compact row -> g_tmp (ascending cols), count nnz
    // ------------------------------------------------------------------
    int len = 0;
    {
        const float* wrow = W + (size_t)row * N_RES;
        uint2* tmp = g_tmp + rowbase;
        int cnt = 0;
        #pragma unroll 4
        for (int c0 = 0; c0 < N_RES; c0 += 32) {
            float v = wrow[c0 + lane];
            unsigned m = __ballot_sync(0xffffffffu, v != 0.0f);
            if (v != 0.0f) {
                int pos = cnt + __popc(m & ((1u << lane) - 1u));
                if (pos < ROW_CAP)
                    tmp[pos] = make_uint2(__float_as_uint(v), (unsigned)(c0 + lane));
            }
            cnt += __popc(m);
        }
        len = (cnt < ROW_CAP) ? cnt : ROW_CAP;
    }

    // ------------------------------------------------------------------
    // Phase 1.5: bank round-robin reorder, SoA scatter, fixed 512 pad
    //   pos sorted by (m, bank); sigma: pos = 64k + 32c + l -> s = 64k + 2l + c
    //   pad entries: val=0, col=0 (smem broadcast, conflict-free)
    // ------------------------------------------------------------------
    {
        int* cnt = cnt_sm + wid * 32;
        cnt[lane] = 0;
        __syncwarp();

        uint2* tmp = g_tmp + rowbase;
        for (int j = lane; j < len; j += 32) {          // pass A: within-bank idx
            uint2 e = tmp[j];
            int b = (int)(e.y & 31u);
            int m = atomicAdd(&cnt[b], 1);
            tmp[j].y = e.y | ((unsigned)m << 16);
        }
        __syncwarp();

        for (int j = lane; j < ROW_CAP; j += 32) {      // zero-fill all 512
            g_val[rowbase + j] = 0.0f;
            g_col[rowbase + j] = 0;
        }
        __syncwarp();

        for (int j = lane; j < len; j += 32) {          // pass B: rank+sigma+scatter
            uint2 e = tmp[j];
            int col = (int)(e.y & 0xFFFu);
            int m   = (int)(e.y >> 16);
            int b   = col & 31;
            int pos = 0;
            #pragma unroll
            for (int b2 = 0; b2 < 32; ++b2) {
                int c = cnt[b2];
                pos += (c < m ? c : m) + (int)((b2 < b) && (c > m));
            }
            int s = (pos & ~63) | ((pos & 31) << 1) | ((pos >> 5) & 1);
            g_val[rowbase + s] = __uint_as_float(e.x);
            g_col[rowbase + s] = (unsigned short)col;
        }
    }
    __syncthreads();

    // ------------------------------------------------------------------
    // Hoist loop-invariants: W_in row + the 16 weight values (R10 balance:
    // cols stay in L1, re-loaded per step -> lower reg pressure)
    // ------------------------------------------------------------------
    const float a  = LEAK;
    const float ia = 1.0f - LEAK;
    const float4 w4 = __ldg((const float4*)(W_in + (size_t)row * N_IN) + lane);

    float2 V[8];
    {
        const float2* vp = (const float2*)(g_val + rowbase);
        #pragma unroll
        for (int k = 0; k < 8; ++k) V[k] = vp[(k << 5) + lane];
    }
    const unsigned int* cp = (const unsigned int*)(g_col + rowbase);

    // ------------------------------------------------------------------
    // Phase 2: time recurrence
    // ------------------------------------------------------------------
    float4 x4 = __ldg((const float4*)(x) + lane);      // prefetched x_0

    for (int t = 0; t < T_STEPS; ++t) {
        // ---- global gate FIRST (x for this step is already in registers;
        //      the spinner has no pending memory wait before polling) ----
        if (t > 0) {
            if (tid == 0) {
                const unsigned int want = (unsigned int)t * BLOCKS;
                // 2-deep staggered poll: check the older value while the
                // newer load is in flight -> ~2x finer detection.
                unsigned int va = ld_relaxed_gpu(&g_barrier);
                while (true) {
                    unsigned int vb = ld_relaxed_gpu(&g_barrier);
                    if (va >= want) break;
                    va = vb;
                }
            }
            __syncthreads();   // S1
        }

        // bulk stage h_{t-1} into smem (L2-direct, always coherent)
        if (t == 0) {
            for (int i = tid; i < N_RES; i += THREADS) h_sm[i] = 0.0f;
        } else {
            const float4* hprev = (const float4*)(out + (size_t)(t - 1) * N_RES);
            float4 v = __ldcg(hprev + tid);
            *(float4*)(h_sm + tid * 4) = v;
        }
        __syncthreads();       // S2

        // dense x part (registers only) + issue prefetch of x_{t+1}
        float sum0 = w4.x * x4.x + w4.y * x4.y;
        float sum1 = w4.z * x4.z + w4.w * x4.w;
        if (t + 1 < T_STEPS)
            x4 = __ldg((const float4*)(x + (size_t)(t + 1) * N_IN) + lane);

        // uniform 8-iteration conflict-free gather; vals from registers
        #pragma unroll
        for (int k = 0; k < 8; ++k) {
            unsigned int cc = cp[(k << 5) + lane];
            sum0 = fmaf(V[k].x, h_sm[cc & 0xFFFFu], sum0);
            sum1 = fmaf(V[k].y, h_sm[cc >> 16],     sum1);
        }

        // butterfly warp reduce
        float sum = sum0 + sum1;
        #pragma unroll
        for (int o = 16; o > 0; o >>= 1)
            sum += __shfl_xor_sync(0xffffffffu, sum, o);

        if (lane == 0) {
            float hn = ia * h_sm[row] + a * tanhf(sum);
            __stcg(out + (size_t)t * N_RES + row, hn);
        }

        if (t < T_STEPS - 1) {
            __syncthreads();                 // S3: all rows of this block in L2
            if (tid == 0) red_release_gpu_add(&g_barrier, 1u);
        }
    }
}

extern "C" void kernel_launch(void* const* d_in, const int* in_sizes, int n_in,
                              void* d_out, int out_size)
{
    const float* x    = (const float*)d_in[0];   // [2048, 128]
    const float* W_in = (const float*)d_in[1];   // [4096, 128]
    const float* W    = (const float*)d_in[2];   // [4096, 4096]
    float* out        = (float*)d_out;           // [2048, 4096]

    esn_reset_kernel<<<1, 1>>>();
    esn_kernel<<<BLOCKS, THREADS>>>(x, W_in, W, out);
}

// round 13
// speedup vs baseline: 1.1722x; 1.0270x over previous
#include <cuda_runtime.h>
#include <cstdint>

// ---------------------------------------------------------------------------
// SimpleESN: h_t = (1-a) h_{t-1} + a * tanh(W_in x_t + W h_{t-1})
//
// R13 = R10 (anchor: V-hoisted, uniform 8 iters, single-counter relay) with
// the input projection LIFTED OUT of the recurrence:
//  - u[t][r] = W_in[r] . x_t precomputed for ALL t by a one-shot GEMM kernel
//    (~85us). The step loop loses w4+x4 (-8 regs) and its only pre-gate op
//    is a dependency-free 4B broadcast load -> the spinner warp polls
//    immediately, never stalled by an x_t L1 miss (was ~262+ cyc/step).
//  - 2-deep staggered poll (register-free, spinner only).
// ---------------------------------------------------------------------------

#define T_STEPS 2048
#define N_RES   4096
#define N_IN    128
#define LEAK    0.3f

#define BLOCKS  128
#define THREADS 1024
#define WARPS   (THREADS / 32)                 // 32
#define ROWS_PER_BLOCK (N_RES / BLOCKS)        // 32 -> 1 row per warp
#define ROW_CAP 512                            // FIXED: 8 iters for all rows
#define GT      16                             // t-values per GEMM block

__device__ uint2          g_tmp[(size_t)N_RES * ROW_CAP];   // build scratch
__device__ float          g_val[(size_t)N_RES * ROW_CAP];
__device__ unsigned short g_col[(size_t)N_RES * ROW_CAP];
__device__ float          g_u[(size_t)T_STEPS * N_RES];     // 33.5 MB: W_in@x_t
__device__ unsigned int   g_barrier;

__global__ void esn_reset_kernel() { g_barrier = 0u; }

__device__ __forceinline__ unsigned int ld_relaxed_gpu(const unsigned int* p) {
    unsigned int v;
    asm volatile("ld.relaxed.gpu.global.u32 %0, [%1];" : "=r"(v) : "l"(p) : "memory");
    return v;
}
__device__ __forceinline__ void red_release_gpu_add(unsigned int* p, unsigned int v) {
    asm volatile("red.release.gpu.global.add.u32 [%0], %1;" :: "l"(p), "r"(v) : "memory");
}

// ---------------------------------------------------------------------------
// One-shot input projection: u[t][row] = W_in[row] . x[t]
// Block b covers t in [16b, 16b+16); thread covers rows tid, tid+1024, ...
// ---------------------------------------------------------------------------
__global__ void __launch_bounds__(1024, 1)
gemm_u_kernel(const float* __restrict__ x, const float* __restrict__ W_in)
{
    __shared__ float4 xs[GT][N_IN / 4];                // 16 t x 32 float4 = 8 KB
    const int tid = threadIdx.x;
    const int t0  = blockIdx.x * GT;

    if (tid < GT * (N_IN / 4)) {
        int tt = tid >> 5, k4 = tid & 31;
        xs[tt][k4] = __ldg((const float4*)(x + (size_t)(t0 + tt) * N_IN) + k4);
    }
    __syncthreads();

    const float4* w4p = (const float4*)W_in;
    #pragma unroll
    for (int rr = 0; rr < N_RES / 1024; ++rr) {
        const int row = rr * 1024 + tid;
        float acc[GT];
        #pragma unroll
        for (int t = 0; t < GT; ++t) acc[t] = 0.0f;

        #pragma unroll 4
        for (int k4 = 0; k4 < N_IN / 4; ++k4) {
            float4 w = __ldg(w4p + (size_t)row * (N_IN / 4) + k4);
            #pragma unroll
            for (int t = 0; t < GT; ++t) {
                float4 xv = xs[t][k4];
                acc[t] = fmaf(w.x, xv.x, acc[t]);
                acc[t] = fmaf(w.y, xv.y, acc[t]);
                acc[t] = fmaf(w.z, xv.z, acc[t]);
                acc[t] = fmaf(w.w, xv.w, acc[t]);
            }
        }
        #pragma unroll
        for (int t = 0; t < GT; ++t)
            g_u[(size_t)(t0 + t) * N_RES + row] = acc[t];
    }
}

__global__ void __launch_bounds__(THREADS, 1)
esn_kernel(const float* __restrict__ W, float* __restrict__ out)
{
    __shared__ float h_sm[N_RES];                      // 16 KB
    __shared__ int   cnt_sm[WARPS * 32];               // 4 KB: build-phase bins

    const int tid  = threadIdx.x;
    const int wid  = tid >> 5;
    const int lane = tid & 31;
    const int row0 = blockIdx.x * ROWS_PER_BLOCK;
    const int row  = row0 + wid;
    const size_t rowbase = (size_t)row * ROW_CAP;

    // ------------------------------------------------------------------
    // Phase 1: compact row -> g_tmp (ascending cols), count nnz
    // ------------------------------------------------------------------
    int len = 0;
    {
        const float* wrow = W + (size_t)row * N_RES;
        uint2* tmp = g_tmp + rowbase;
        int cnt = 0;
        #pragma unroll 4
        for (int c0 = 0; c0 < N_RES; c0 += 32) {
            float v = wrow[c0 + lane];
            unsigned m = __ballot_sync(0xffffffffu, v != 0.0f);
            if (v != 0.0f) {
                int pos = cnt + __popc(m & ((1u << lane) - 1u));
                if (pos < ROW_CAP)
                    tmp[pos] = make_uint2(__float_as_uint(v), (unsigned)(c0 + lane));
            }
            cnt += __popc(m);
        }
        len = (cnt < ROW_CAP) ? cnt : ROW_CAP;
    }

    // ------------------------------------------------------------------
    // Phase 1.5: bank round-robin reorder, SoA scatter, fixed 512 pad
    //   pos sorted by (m, bank); sigma: pos = 64k + 32c + l -> s = 64k + 2l + c
    //   pad entries: val=0, col=0 (smem broadcast, conflict-free)
    // ------------------------------------------------------------------
    {
        int* cnt = cnt_sm + wid * 32;
        cnt[lane] = 0;
        __syncwarp();

        uint2* tmp = g_tmp + rowbase;
        for (int j = lane; j < len; j += 32) {          // pass A: within-bank idx
            uint2 e = tmp[j];
            int b = (int)(e.y & 31u);
            int m = atomicAdd(&cnt[b], 1);
            tmp[j].y = e.y | ((unsigned)m << 16);
        }
        __syncwarp();

        for (int j = lane; j < ROW_CAP; j += 32) {      // zero-fill all 512
            g_val[rowbase + j] = 0.0f;
            g_col[rowbase + j] = 0;
        }
        __syncwarp();

        for (int j = lane; j < len; j += 32) {          // pass B: rank+sigma+scatter
            uint2 e = tmp[j];
            int col = (int)(e.y & 0xFFFu);
            int m   = (int)(e.y >> 16);
            int b   = col & 31;
            int pos = 0;
            #pragma unroll
            for (int b2 = 0; b2 < 32; ++b2) {
                int c = cnt[b2];
                pos += (c < m ? c : m) + (int)((b2 < b) && (c > m));
            }
            int s = (pos & ~63) | ((pos & 31) << 1) | ((pos >> 5) & 1);
            g_val[rowbase + s] = __uint_as_float(e.x);
            g_col[rowbase + s] = (unsigned short)col;
        }
    }
    __syncthreads();

    // ------------------------------------------------------------------
    // Hoist loop-invariants: the 16 weight values (cols stay in L1)
    // ------------------------------------------------------------------
    const float a  = LEAK;
    const float ia = 1.0f - LEAK;
    float2 V[8];
    {
        const float2* vp = (const float2*)(g_val + rowbase);
        #pragma unroll
        for (int k = 0; k < 8; ++k) V[k] = vp[(k << 5) + lane];
    }
    const unsigned int* cp = (const unsigned int*)(g_col + rowbase);

    // ------------------------------------------------------------------
    // Phase 2: time recurrence (sync scheme = R5/R10)
    // ------------------------------------------------------------------
    for (int t = 0; t < T_STEPS; ++t) {
        // input projection: ONE dependency-free 4B broadcast load; the
        // spinner's poll below never waits on it
        float uin = __ldcg(g_u + (size_t)t * N_RES + row);

        // global gate: single spinner, 2-deep staggered poll
        if (t > 0) {
            if (tid == 0) {
                const unsigned int want = (unsigned int)t * BLOCKS;
                unsigned int va = ld_relaxed_gpu(&g_barrier);
                while (true) {
                    unsigned int vb = ld_relaxed_gpu(&g_barrier);
                    if (va >= want) break;
                    va = vb;
                }
            }
            __syncthreads();   // S1
        }

        // bulk stage h_{t-1} into smem (L2-direct, always coherent)
        if (t == 0) {
            for (int i = tid; i < N_RES; i += THREADS) h_sm[i] = 0.0f;
        } else {
            const float4* hprev = (const float4*)(out + (size_t)(t - 1) * N_RES);
            float4 v = __ldcg(hprev + tid);
            *(float4*)(h_sm + tid * 4) = v;
        }
        __syncthreads();       // S2

        // uniform 8-iteration conflict-free gather; vals from registers
        float sum0 = 0.0f, sum1 = 0.0f;
        #pragma unroll
        for (int k = 0; k < 8; ++k) {
            unsigned int cc = cp[(k << 5) + lane];
            sum0 = fmaf(V[k].x, h_sm[cc & 0xFFFFu], sum0);
            sum1 = fmaf(V[k].y, h_sm[cc >> 16],     sum1);
        }

        // butterfly warp reduce
        float sum = sum0 + sum1;
        #pragma unroll
        for (int o = 16; o > 0; o >>= 1)
            sum += __shfl_xor_sync(0xffffffffu, sum, o);

        if (lane == 0) {
            float hn = ia * h_sm[row] + a * tanhf(sum + uin);
            __stcg(out + (size_t)t * N_RES + row, hn);
        }

        if (t < T_STEPS - 1) {
            __syncthreads();                 // S3: all rows of this block in L2
            if (tid == 0) red_release_gpu_add(&g_barrier, 1u);
        }
    }
}

extern "C" void kernel_launch(void* const* d_in, const int* in_sizes, int n_in,
                              void* d_out, int out_size)
{
    const float* x    = (const float*)d_in[0];   // [2048, 128]
    const float* W_in = (const float*)d_in[1];   // [4096, 128]
    const float* W    = (const float*)d_in[2];   // [4096, 4096]
    float* out        = (float*)d_out;           // [2048, 4096]

    esn_reset_kernel<<<1, 1>>>();
    gemm_u_kernel<<<T_STEPS / GT, 1024>>>(x, W_in);
    esn_kernel<<<BLOCKS, THREADS>>>(W, out);
}

// round 14
// speedup vs baseline: 1.2603x; 1.0752x over previous
#include <cuda_runtime.h>
#include <cstdint>

// ---------------------------------------------------------------------------
// SimpleESN: h_t = (1-a) h_{t-1} + a * tanh(W_in x_t + W h_{t-1})
//
// R14 = R10 (anchor) + u-precompute + vectorized col loads.
//  - sync: EXACT R10 scheme (single counter, simple one-load poll, S1/S2/S3).
//    R12/R13's 2-deep poll regressed ~500us: extra loads on the line being
//    release-RED'd cause LTS replays -> reverted.
//  - u[t][r] = W_in[r].x_t precomputed by a one-shot GEMM (~80us); step-loop
//    head is one dependency-free 4B broadcast load (spinner polls instantly).
//  - cols relaid out so each lane's 16 indices are 32B contiguous:
//    2x LDG.128 per step instead of 8x LDG.32 (same LDS gather pattern).
//  - V[8] value regs hoisted, uniform 8 iters, conflict-free banks (as R10).
// ---------------------------------------------------------------------------

#define T_STEPS 2048
#define N_RES   4096
#define N_IN    128
#define LEAK    0.3f

#define BLOCKS  128
#define THREADS 1024
#define WARPS   (THREADS / 32)                 // 32
#define ROWS_PER_BLOCK (N_RES / BLOCKS)        // 32 -> 1 row per warp
#define ROW_CAP 512                            // FIXED: 8 iters for all rows
#define GT      16                             // t-values per GEMM block

__device__ uint2          g_tmp[(size_t)N_RES * ROW_CAP];   // build scratch
__device__ float          g_val[(size_t)N_RES * ROW_CAP];
__device__ unsigned short g_col[(size_t)N_RES * ROW_CAP];
__device__ float          g_u[(size_t)T_STEPS * N_RES];     // 33.5 MB: W_in@x_t
__device__ unsigned int   g_barrier;

__device__ __forceinline__ unsigned int ld_relaxed_gpu(const unsigned int* p) {
    unsigned int v;
    asm volatile("ld.relaxed.gpu.global.u32 %0, [%1];" : "=r"(v) : "l"(p) : "memory");
    return v;
}
__device__ __forceinline__ void red_release_gpu_add(unsigned int* p, unsigned int v) {
    asm volatile("red.release.gpu.global.add.u32 [%0], %1;" :: "l"(p), "r"(v) : "memory");
}

// ---------------------------------------------------------------------------
// One-shot input projection: u[t][row] = W_in[row] . x[t]
// Also resets the relay counter (block 0) -- runs before esn in-stream.
// ---------------------------------------------------------------------------
__global__ void __launch_bounds__(1024, 1)
gemm_u_kernel(const float* __restrict__ x, const float* __restrict__ W_in)
{
    __shared__ float4 xs[GT][N_IN / 4];                // 8 KB
    const int tid = threadIdx.x;
    const int t0  = blockIdx.x * GT;

    if (blockIdx.x == 0 && tid == 0) g_barrier = 0u;

    if (tid < GT * (N_IN / 4)) {
        int tt = tid >> 5, k4 = tid & 31;
        xs[tt][k4] = __ldg((const float4*)(x + (size_t)(t0 + tt) * N_IN) + k4);
    }
    __syncthreads();

    const float4* w4p = (const float4*)W_in;
    #pragma unroll
    for (int rr = 0; rr < N_RES / 1024; ++rr) {
        const int row = rr * 1024 + tid;
        float acc[GT];
        #pragma unroll
        for (int t = 0; t < GT; ++t) acc[t] = 0.0f;

        #pragma unroll 4
        for (int k4 = 0; k4 < N_IN / 4; ++k4) {
            float4 w = __ldg(w4p + (size_t)row * (N_IN / 4) + k4);
            #pragma unroll
            for (int t = 0; t < GT; ++t) {
                float4 xv = xs[t][k4];
                acc[t] = fmaf(w.x, xv.x, acc[t]);
                acc[t] = fmaf(w.y, xv.y, acc[t]);
                acc[t] = fmaf(w.z, xv.z, acc[t]);
                acc[t] = fmaf(w.w, xv.w, acc[t]);
            }
        }
        #pragma unroll
        for (int t = 0; t < GT; ++t)
            g_u[(size_t)(t0 + t) * N_RES + row] = acc[t];
    }
}

__global__ void __launch_bounds__(THREADS, 1)
esn_kernel(const float* __restrict__ W, float* __restrict__ out)
{
    __shared__ float h_sm[N_RES];                      // 16 KB
    __shared__ int   cnt_sm[WARPS * 32];               // 4 KB: build-phase bins

    const int tid  = threadIdx.x;
    const int wid  = tid >> 5;
    const int lane = tid & 31;
    const int row0 = blockIdx.x * ROWS_PER_BLOCK;
    const int row  = row0 + wid;
    const size_t rowbase = (size_t)row * ROW_CAP;

    // ------------------------------------------------------------------
    // Phase 1: compact row -> g_tmp (ascending cols), count nnz
    // ------------------------------------------------------------------
    int len = 0;
    {
        const float* wrow = W + (size_t)row * N_RES;
        uint2* tmp = g_tmp + rowbase;
        int cnt = 0;
        #pragma unroll 4
        for (int c0 = 0; c0 < N_RES; c0 += 32) {
            float v = wrow[c0 + lane];
            unsigned m = __ballot_sync(0xffffffffu, v != 0.0f);
            if (v != 0.0f) {
                int pos = cnt + __popc(m & ((1u << lane) - 1u));
                if (pos < ROW_CAP)
                    tmp[pos] = make_uint2(__float_as_uint(v), (unsigned)(c0 + lane));
            }
            cnt += __popc(m);
        }
        len = (cnt < ROW_CAP) ? cnt : ROW_CAP;
    }

    // ------------------------------------------------------------------
    // Phase 1.5: bank round-robin reorder, fixed 512 pad, SoA scatter.
    //   logical slot s (sorted by (m, bank)): s = 64k + 2l + c
    //   vals stored AT s (V-hoist reads float2 (k<<5)+l).
    //   cols stored PERMUTED so lane l's 16 cols are contiguous 32B:
    //     col index = 16l + 2k + c  ->  two uint4 loads per lane per step.
    //   pad entries: val=0, col=0 (smem broadcast, conflict-free)
    // ------------------------------------------------------------------
    {
        int* cnt = cnt_sm + wid * 32;
        cnt[lane] = 0;
        __syncwarp();

        uint2* tmp = g_tmp + rowbase;
        for (int j = lane; j < len; j += 32) {          // pass A: within-bank idx
            uint2 e = tmp[j];
            int b = (int)(e.y & 31u);
            int m = atomicAdd(&cnt[b], 1);
            tmp[j].y = e.y | ((unsigned)m << 16);
        }
        __syncwarp();

        for (int j = lane; j < ROW_CAP; j += 32) {      // zero-fill all 512
            g_val[rowbase + j] = 0.0f;
            g_col[rowbase + j] = 0;
        }
        __syncwarp();

        for (int j = lane; j < len; j += 32) {          // pass B: rank+scatter
            uint2 e = tmp[j];
            int col = (int)(e.y & 0xFFFu);
            int m   = (int)(e.y >> 16);
            int b   = col & 31;
            int pos = 0;
            #pragma unroll
            for (int b2 = 0; b2 < 32; ++b2) {
                int c = cnt[b2];
                pos += (c < m ? c : m) + (int)((b2 < b) && (c > m));
            }
            int s = (pos & ~63) | ((pos & 31) << 1) | ((pos >> 5) & 1);
            int k = s >> 6, l = (s >> 1) & 31, cc = s & 1;
            g_val[rowbase + s] = __uint_as_float(e.x);
            g_col[rowbase + (l << 4) + (k << 1) + cc] = (unsigned short)col;
        }
    }
    __syncthreads();

    // ------------------------------------------------------------------
    // Hoist loop-invariants: the 16 weight values (cols re-LDG'd per step)
    // ------------------------------------------------------------------
    const float a  = LEAK;
    const float ia = 1.0f - LEAK;
    float2 V[8];
    {
        const float2* vp = (const float2*)(g_val + rowbase);
        #pragma unroll
        for (int k = 0; k < 8; ++k) V[k] = vp[(k << 5) + lane];
    }
    const uint4* cpv = (const uint4*)(g_col + rowbase) + (lane << 1);

    // ------------------------------------------------------------------
    // Phase 2: time recurrence (sync scheme = R5/R10 exactly)
    // ------------------------------------------------------------------
    for (int t = 0; t < T_STEPS; ++t) {
        // input projection: ONE dependency-free 4B broadcast load
        float uin = __ldcg(g_u + (size_t)t * N_RES + row);

        // global gate: single spinner, simple self-throttled poll
        if (t > 0) {
            if (tid == 0) {
                const unsigned int want = (unsigned int)t * BLOCKS;
                while (ld_relaxed_gpu(&g_barrier) < want) { }
            }
            __syncthreads();   // S1
        }

        // bulk stage h_{t-1} into smem (L2-direct, always coherent)
        if (t == 0) {
            for (int i = tid; i < N_RES; i += THREADS) h_sm[i] = 0.0f;
        } else {
            const float4* hprev = (const float4*)(out + (size_t)(t - 1) * N_RES);
            float4 v = __ldcg(hprev + tid);
            *(float4*)(h_sm + tid * 4) = v;
        }
        __syncthreads();       // S2

        // uniform 8-iteration conflict-free gather; vals in regs, cols via
        // two LDG.128 (lane's 16 cols are 32B contiguous)
        uint4 ca = __ldg(cpv);
        uint4 cb = __ldg(cpv + 1);
        unsigned int cc[8] = {ca.x, ca.y, ca.z, ca.w, cb.x, cb.y, cb.z, cb.w};
        float sum0 = 0.0f, sum1 = 0.0f;
        #pragma unroll
        for (int k = 0; k < 8; ++k) {
            sum0 = fmaf(V[k].x, h_sm[cc[k] & 0xFFFFu], sum0);
            sum1 = fmaf(V[k].y, h_sm[cc[k] >> 16],     sum1);
        }

        // butterfly warp reduce
        float sum = sum0 + sum1;
        #pragma unroll
        for (int o = 16; o > 0; o >>= 1)
            sum += __shfl_xor_sync(0xffffffffu, sum, o);

        if (lane == 0) {
            float hn = ia * h_sm[row] + a * tanhf(sum + uin);
            __stcg(out + (size_t)t * N_RES + row, hn);
        }

        if (t < T_STEPS - 1) {
            __syncthreads();                 // S3: all rows of this block in L2
            if (tid == 0) red_release_gpu_add(&g_barrier, 1u);
        }
    }
}

extern "C" void kernel_launch(void* const* d_in, const int* in_sizes, int n_in,
                              void* d_out, int out_size)
{
    const float* x    = (const float*)d_in[0];   // [2048, 128]
    const float* W_in = (const float*)d_in[1];   // [4096, 128]
    const float* W    = (const float*)d_in[2];   // [4096, 4096]
    float* out        = (float*)d_out;           // [2048, 4096]

    gemm_u_kernel<<<T_STEPS / GT, 1024>>>(x, W_in);
    esn_kernel<<<BLOCKS, THREADS>>>(W, out);
}